// round 7
// baseline (speedup 1.0000x reference)
#include <cuda_runtime.h>
#include <cstdint>

// Problem constants (fixed by the dataset)
#define NN   100000
#define EE   400000
#define RR   4
#define DIN  128
#define COLS 640         // R*128 + 128 self-loop
#define NBUK (RR * NN)   // CSR buckets

// ---------------- device scratch (static, no allocation) ----------------
__device__ float g_Bt[2][COLS * DIN];              // packed weights per layer [c][k]
__device__ float g_Wh[(size_t)RR * NN * DIN];      // relation-major Wh [r][n][128]
__device__ float g_h1[(size_t)NN * DIN];           // layer-1 output
__device__ float g_el[(size_t)RR * NN * 8];
__device__ float g_er[(size_t)RR * NN * 8];
// CSR
__device__ int g_cnt[NBUK];
__device__ int g_off[NBUK + 1];
__device__ int g_cur[NBUK];
__device__ int g_bsum[1024];
__device__ int g_esrc[RR * EE];                    // src per edge, bucketed by (r,dst)

// ---------------- helpers ----------------
__device__ __forceinline__ float tf32_rn(float x) {
    uint32_t u;
    asm("cvt.rna.tf32.f32 %0, %1;" : "=r"(u) : "f"(x));
    return __uint_as_float(u);
}
__device__ __forceinline__ void mma_tf32(float* d, const uint32_t* a, const uint32_t* b) {
    asm volatile(
        "mma.sync.aligned.m16n8k8.row.col.f32.tf32.tf32.f32 "
        "{%0,%1,%2,%3}, {%4,%5,%6,%7}, {%8,%9}, {%0,%1,%2,%3};"
        : "+f"(d[0]), "+f"(d[1]), "+f"(d[2]), "+f"(d[3])
        : "r"(a[0]), "r"(a[1]), "r"(a[2]), "r"(a[3]), "r"(b[0]), "r"(b[1]));
}

// ================= CSR build =================
__global__ void zero_cnt() {
    int i = blockIdx.x * blockDim.x + threadIdx.x;
    if (i < NBUK) g_cnt[i] = 0;
}
__global__ void hist_dst(const int* __restrict__ dst) {
    int i = blockIdx.x * blockDim.x + threadIdx.x;
    if (i >= RR * EE) return;
    int r = i / EE;
    atomicAdd(&g_cnt[r * NN + dst[i]], 1);
}
__global__ __launch_bounds__(1024) void scan_blk() {
    __shared__ int s[1024];
    int t = threadIdx.x;
    int i = blockIdx.x * 1024 + t;
    int v = (i < NBUK) ? g_cnt[i] : 0;
    s[t] = v;
    __syncthreads();
#pragma unroll
    for (int off = 1; off < 1024; off <<= 1) {
        int u = (t >= off) ? s[t - off] : 0;
        __syncthreads();
        s[t] += u;
        __syncthreads();
    }
    if (i < NBUK) g_off[i] = s[t] - v;
    if (t == 1023) g_bsum[blockIdx.x] = s[1023];
}
__global__ __launch_bounds__(1024) void scan_part(int nb) {
    __shared__ int s[1024];
    int t = threadIdx.x;
    int v = (t < nb) ? g_bsum[t] : 0;
    s[t] = v;
    __syncthreads();
#pragma unroll
    for (int off = 1; off < 1024; off <<= 1) {
        int u = (t >= off) ? s[t - off] : 0;
        __syncthreads();
        s[t] += u;
        __syncthreads();
    }
    g_bsum[t] = s[t] - v;
}
__global__ void scan_fix() {
    int i = blockIdx.x * blockDim.x + threadIdx.x;
    if (i >= NBUK) return;
    int o = g_off[i] + g_bsum[i >> 10];
    g_off[i] = o;
    g_cur[i] = o;
    if (i == 0) g_off[NBUK] = RR * EE;
}
__global__ void scatter_src(const int* __restrict__ src, const int* __restrict__ dst) {
    int i = blockIdx.x * blockDim.x + threadIdx.x;
    if (i >= RR * EE) return;
    int r = i / EE;
    int pos = atomicAdd(&g_cur[r * NN + dst[i]], 1);
    g_esrc[pos] = src[i];
}

// ---------------- pack weights transposed: g_Bt[slot][c][k], tf32-rounded ----------
__global__ void pack_Bt(const float* __restrict__ W, const float* __restrict__ loop_w,
                        int slot) {
    int idx = blockIdx.x * blockDim.x + threadIdx.x;
    if (idx >= COLS * DIN) return;
    int c = idx >> 7, k = idx & 127;
    float v;
    if (c < RR * 128) {
        int r = c >> 7, j = c & 127;
        v = W[((size_t)r << 14) + (size_t)k * 128 + j];
    } else {
        v = loop_w[(size_t)k * 128 + (c - RR * 128)];
    }
    g_Bt[slot][idx] = tf32_rn(v);
}

// ---------------- tf32 mma GEMM with fused el/er + self-loop epilogue ----------------
// grid (5, ceil(M/128)). bn<4: relation bn -> g_Wh + el/er. bn==4: self-loop+bias -> out.
#define LDS_PITCH 132
#define GEMM_SMEM (2 * 128 * LDS_PITCH * 4)
template <int H, bool RELU_A>
__global__ __launch_bounds__(256, 1) void gemm_fused(const float* __restrict__ Ain, int M,
                                                     const float* __restrict__ al,
                                                     const float* __restrict__ ar,
                                                     const float* __restrict__ bias,
                                                     float* __restrict__ outp, int slot) {
    const float* A = Ain ? Ain : g_h1;
    float* out = outp ? outp : g_h1;
    extern __shared__ float sm[];
    float (*As)[LDS_PITCH] = (float(*)[LDS_PITCH])sm;
    float (*Bs)[LDS_PITCH] = (float(*)[LDS_PITCH])(sm + 128 * LDS_PITCH);
    float (*Cs)[LDS_PITCH] = As;  // reused after MMAs

    int tid = threadIdx.x;
    int wid = tid >> 5, lane = tid & 31;
    int group = lane >> 2, tid4 = lane & 3;
    int warp_m = wid >> 1, warp_n = wid & 1;
    int bn = blockIdx.x, by = blockIdx.y;

    // ---- stage A (tf32-rounded, optional relu) ----
    {
        int row = tid >> 1;
        int colb = (tid & 1) * 64;
        int grow = by * 128 + row;
        const float4* ap = (grow < M) ? (const float4*)(A + (size_t)grow * DIN + colb) : nullptr;
#pragma unroll
        for (int j = 0; j < 16; j++) {
            float4 v = ap ? __ldg(ap + j) : make_float4(0.f, 0.f, 0.f, 0.f);
            if (RELU_A) {
                v.x = fmaxf(v.x, 0.f); v.y = fmaxf(v.y, 0.f);
                v.z = fmaxf(v.z, 0.f); v.w = fmaxf(v.w, 0.f);
            }
            *(float4*)(&As[row][colb + j * 4]) =
                make_float4(tf32_rn(v.x), tf32_rn(v.y), tf32_rn(v.z), tf32_rn(v.w));
        }
    }
    // ---- stage B ----
    {
        int row = tid >> 1;
        int colb = (tid & 1) * 64;
        const float4* bp = (const float4*)(g_Bt[slot] + (size_t)(bn * 128 + row) * DIN + colb);
#pragma unroll
        for (int j = 0; j < 16; j++)
            *(float4*)(&Bs[row][colb + j * 4]) = __ldg(bp + j);
    }
    __syncthreads();

    float acc[2][8][4] = {};
    int m0 = warp_m * 32;
    int n0 = warp_n * 64;

#pragma unroll
    for (int ks = 0; ks < 16; ks++) {
        int k0 = ks * 8;
        uint32_t afr[2][4];
#pragma unroll
        for (int mt = 0; mt < 2; mt++) {
            int mr = m0 + mt * 16;
            afr[mt][0] = __float_as_uint(As[mr + group][k0 + tid4]);
            afr[mt][1] = __float_as_uint(As[mr + group + 8][k0 + tid4]);
            afr[mt][2] = __float_as_uint(As[mr + group][k0 + tid4 + 4]);
            afr[mt][3] = __float_as_uint(As[mr + group + 8][k0 + tid4 + 4]);
        }
#pragma unroll
        for (int nt = 0; nt < 8; nt++) {
            int nc = n0 + nt * 8;
            uint32_t bfr[2];
            bfr[0] = __float_as_uint(Bs[nc + group][k0 + tid4]);
            bfr[1] = __float_as_uint(Bs[nc + group][k0 + tid4 + 4]);
            mma_tf32(acc[0][nt], afr[0], bfr);
            mma_tf32(acc[1][nt], afr[1], bfr);
        }
    }

    if (bn < RR) {
        // ---- store Wh tile (relation-major) ----
#pragma unroll
        for (int mt = 0; mt < 2; mt++) {
            int row = by * 128 + m0 + mt * 16 + group;
#pragma unroll
            for (int nt = 0; nt < 8; nt++) {
                int col = n0 + nt * 8 + tid4 * 2;
                if (row < M)
                    *(float2*)(g_Wh + ((size_t)bn * NN + row) * DIN + col) =
                        make_float2(acc[mt][nt][0], acc[mt][nt][1]);
                if (row + 8 < M)
                    *(float2*)(g_Wh + ((size_t)bn * NN + row + 8) * DIN + col) =
                        make_float2(acc[mt][nt][2], acc[mt][nt][3]);
            }
        }
        // ---- stage C into smem for el/er ----
        __syncthreads();
#pragma unroll
        for (int mt = 0; mt < 2; mt++) {
            int rl = m0 + mt * 16 + group;
#pragma unroll
            for (int nt = 0; nt < 8; nt++) {
                int cl = n0 + nt * 8 + tid4 * 2;
                *(float2*)(&Cs[rl][cl]) = make_float2(acc[mt][nt][0], acc[mt][nt][1]);
                *(float2*)(&Cs[rl + 8][cl]) = make_float2(acc[mt][nt][2], acc[mt][nt][3]);
            }
        }
        __syncthreads();
        // ---- el/er: 8 warps x 16 rows ----
        float4 a4 = __ldg((const float4*)(al + bn * 128 + lane * 4));
        float4 b4 = __ldg((const float4*)(ar + bn * 128 + lane * 4));
#pragma unroll 4
        for (int rr = 0; rr < 16; rr++) {
            int row = wid * 16 + rr;
            int grow = by * 128 + row;
            float4 v = *(const float4*)(&Cs[row][lane * 4]);
            float pl = v.x * a4.x + v.y * a4.y + v.z * a4.z + v.w * a4.w;
            float pr = v.x * b4.x + v.y * b4.y + v.z * b4.z + v.w * b4.w;
            if (H == 8) {
                pl += __shfl_xor_sync(~0u, pl, 1);
                pr += __shfl_xor_sync(~0u, pr, 1);
                pl += __shfl_xor_sync(~0u, pl, 2);
                pr += __shfl_xor_sync(~0u, pr, 2);
                if ((lane & 3) == 0 && grow < M) {
                    size_t o = ((size_t)bn * NN + grow) * 8 + (lane >> 2);
                    g_el[o] = pl;
                    g_er[o] = pr;
                }
            } else {
#pragma unroll
                for (int o = 16; o > 0; o >>= 1) {
                    pl += __shfl_xor_sync(~0u, pl, o);
                    pr += __shfl_xor_sync(~0u, pr, o);
                }
                if (lane == 0 && grow < M) {
                    g_el[(size_t)bn * NN + grow] = pl;
                    g_er[(size_t)bn * NN + grow] = pr;
                }
            }
        }
    } else {
        // ---- self-loop + bias -> out ----
#pragma unroll
        for (int mt = 0; mt < 2; mt++) {
            int row = by * 128 + m0 + mt * 16 + group;
#pragma unroll
            for (int nt = 0; nt < 8; nt++) {
                int col = n0 + nt * 8 + tid4 * 2;
                float b0 = __ldg(bias + col), b1 = __ldg(bias + col + 1);
                if (row < M)
                    *(float2*)(out + (size_t)row * DIN + col) =
                        make_float2(acc[mt][nt][0] + b0, acc[mt][nt][1] + b1);
                if (row + 8 < M)
                    *(float2*)(out + (size_t)(row + 8) * DIN + col) =
                        make_float2(acc[mt][nt][2] + b0, acc[mt][nt][3] + b1);
            }
        }
    }
}

// ---------------- fused per-node kernel: all relations, register accumulation ----
// Starts from the GEMM-written (self-loop + bias) value in out[d]; overwrites it.
// Gather loop is software-pipelined (prefetch next src/el/row while accumulating).
template <int H>
__global__ __launch_bounds__(256) void node_fused(float* __restrict__ outp, int do_relu) {
    float* out = outp ? outp : g_h1;
    int d = (blockIdx.x * blockDim.x + threadIdx.x) >> 5;
    int lane = threadIdx.x & 31;
    if (d >= NN) return;

    float4 acc = *(const float4*)(out + (size_t)d * DIN + lane * 4);

#pragma unroll
    for (int r = 0; r < RR; r++) {
        int base = r * NN + d;
        int start = g_off[base];
        int end = g_off[base + 1];
        if (start >= end) continue;
        const float* whr = g_Wh + (size_t)r * NN * DIN;
        const float* elr = g_el + (size_t)r * NN * H;

        if (H == 8) {
            int hl = lane & 7;
            float er_l = g_er[(size_t)base * 8 + hl];
            float den = 0.f;
            for (int c = start + (lane >> 3); c < end; c += 4) {
                int s = __ldg(&g_esrc[c]);
                float e = __ldg(&elr[(size_t)s * 8 + hl]) + er_l;
                e = e > 0.f ? e : 0.2f * e;
                den += expf(e);
            }
            den += __shfl_xor_sync(~0u, den, 8);
            den += __shfl_xor_sync(~0u, den, 16);
            float rden = 1.0f / den;
            int hh = lane >> 2;
            float rden_h = __shfl_sync(~0u, rden, hh);
            float er_h = __shfl_sync(~0u, er_l, hh);

            // pipelined gather
            int c = start;
            int s = __ldg(&g_esrc[c]);
            float4 w = __ldg((const float4*)(whr + (size_t)s * DIN) + lane);
            float el_c = __ldg(&elr[(size_t)s * 8 + hh]);
            for (;;) {
                int cn = c + 1;
                bool more = cn < end;
                int sn = 0;
                float4 wn;
                float eln = 0.f;
                if (more) {
                    sn = __ldg(&g_esrc[cn]);
                    wn = __ldg((const float4*)(whr + (size_t)sn * DIN) + lane);
                    eln = __ldg(&elr[(size_t)sn * 8 + hh]);
                }
                float e = el_c + er_h;
                e = e > 0.f ? e : 0.2f * e;
                float alpha = expf(e) * rden_h;
                acc.x += alpha * w.x;
                acc.y += alpha * w.y;
                acc.z += alpha * w.z;
                acc.w += alpha * w.w;
                if (!more) break;
                c = cn; s = sn; w = wn; el_c = eln;
            }
        } else {
            float er_l = g_er[base];
            float den = 0.f;
            for (int c = start + lane; c < end; c += 32) {
                int s = __ldg(&g_esrc[c]);
                float e = __ldg(&elr[s]) + er_l;
                e = e > 0.f ? e : 0.2f * e;
                den += expf(e);
            }
#pragma unroll
            for (int o = 16; o > 0; o >>= 1) den += __shfl_xor_sync(~0u, den, o);
            float rden = 1.0f / den;

            // pipelined gather
            int c = start;
            int s = __ldg(&g_esrc[c]);
            float4 w = __ldg((const float4*)(whr + (size_t)s * DIN) + lane);
            float el_c = __ldg(&elr[s]);
            for (;;) {
                int cn = c + 1;
                bool more = cn < end;
                int sn = 0;
                float4 wn;
                float eln = 0.f;
                if (more) {
                    sn = __ldg(&g_esrc[cn]);
                    wn = __ldg((const float4*)(whr + (size_t)sn * DIN) + lane);
                    eln = __ldg(&elr[sn]);
                }
                float e = el_c + er_l;
                e = e > 0.f ? e : 0.2f * e;
                float alpha = expf(e) * rden;
                acc.x += alpha * w.x;
                acc.y += alpha * w.y;
                acc.z += alpha * w.z;
                acc.w += alpha * w.w;
                if (!more) break;
                c = cn; s = sn; w = wn; el_c = eln;
            }
        }
    }

    if (do_relu) {
        acc.x = fmaxf(acc.x, 0.f);
        acc.y = fmaxf(acc.y, 0.f);
        acc.z = fmaxf(acc.z, 0.f);
        acc.w = fmaxf(acc.w, 0.f);
    }
    *(float4*)(out + (size_t)d * DIN + lane * 4) = acc;
}

extern "C" void kernel_launch(void* const* d_in, const int* in_sizes, int n_in,
                              void* d_out, int out_size) {
    const float* h   = (const float*)d_in[0];
    const int*   src = (const int*)d_in[1];
    const int*   dst = (const int*)d_in[2];
    const float* W1  = (const float*)d_in[3];
    const float* al1 = (const float*)d_in[4];
    const float* ar1 = (const float*)d_in[5];
    const float* lp1 = (const float*)d_in[6];
    const float* b1  = (const float*)d_in[7];
    const float* W2  = (const float*)d_in[8];
    const float* al2 = (const float*)d_in[9];
    const float* ar2 = (const float*)d_in[10];
    const float* lp2 = (const float*)d_in[11];
    const float* b2  = (const float*)d_in[12];
    float* out = (float*)d_out;

    static cudaStream_t s_side = nullptr;
    static cudaEvent_t ev_fork = nullptr, ev_join = nullptr;
    if (!s_side) {
        cudaFuncSetAttribute(gemm_fused<8, false>,
                             cudaFuncAttributeMaxDynamicSharedMemorySize, GEMM_SMEM);
        cudaFuncSetAttribute(gemm_fused<1, true>,
                             cudaFuncAttributeMaxDynamicSharedMemorySize, GEMM_SMEM);
        cudaStreamCreateWithFlags(&s_side, cudaStreamNonBlocking);
        cudaEventCreateWithFlags(&ev_fork, cudaEventDisableTiming);
        cudaEventCreateWithFlags(&ev_join, cudaEventDisableTiming);
    }

    const int nb1 = (NBUK + 1023) / 1024;
    const dim3 ggrid(RR + 1, (NN + 127) / 128);
    const int nblk = (NN * 32 + 255) / 256;

    // ---- fork: CSR build + layer-2 weight pack on side stream ----
    cudaEventRecord(ev_fork, 0);
    cudaStreamWaitEvent(s_side, ev_fork, 0);
    zero_cnt<<<(NBUK + 255) / 256, 256, 0, s_side>>>();
    hist_dst<<<(RR * EE + 255) / 256, 256, 0, s_side>>>(dst);
    scan_blk<<<nb1, 1024, 0, s_side>>>();
    scan_part<<<1, 1024, 0, s_side>>>(nb1);
    scan_fix<<<(NBUK + 255) / 256, 256, 0, s_side>>>();
    scatter_src<<<(RR * EE + 255) / 256, 256, 0, s_side>>>(src, dst);
    pack_Bt<<<(COLS * DIN + 255) / 256, 256, 0, s_side>>>(W2, lp2, 1);
    cudaEventRecord(ev_join, s_side);

    // ---- main stream: layer-1 pack + GEMM (independent of CSR) ----
    pack_Bt<<<(COLS * DIN + 255) / 256, 256>>>(W1, lp1, 0);
    gemm_fused<8, false><<<ggrid, 256, GEMM_SMEM>>>(h, NN, al1, ar1, b1, nullptr, 0);

    // ---- join, then node pass 1 ----
    cudaStreamWaitEvent(0, ev_join, 0);
    node_fused<8><<<nblk, 256>>>(nullptr, 1);

    // ---- layer 2 ----
    gemm_fused<1, true><<<ggrid, 256, GEMM_SMEM>>>(nullptr, NN, al2, ar2, b2, out, 1);
    node_fused<1><<<nblk, 256>>>(out, 0);

    (void)in_sizes; (void)n_in; (void)out_size;
}

// round 8
// speedup vs baseline: 1.0734x; 1.0734x over previous
#include <cuda_runtime.h>
#include <cuda_fp16.h>
#include <cstdint>

// Problem constants (fixed by the dataset)
#define NN   100000
#define EE   400000
#define RR   4
#define DIN  128
#define COLS 640         // R*128 + 128 self-loop
#define NBUK (RR * NN)   // CSR buckets

// ---------------- device scratch (static, no allocation) ----------------
__device__ float  g_Bt[COLS * DIN];                 // packed weights [c][k], tf32-rounded
__device__ __half g_Wh[(size_t)RR * NN * DIN];      // relation-major Wh [r][n][128], fp16
__device__ float  g_h1[(size_t)NN * DIN];           // layer-1 output
__device__ float  g_el[(size_t)RR * NN * 8];
__device__ float  g_er[(size_t)RR * NN * 8];
// CSR
__device__ int g_cnt[NBUK];
__device__ int g_off[NBUK + 1];
__device__ int g_cur[NBUK];
__device__ int g_bsum[1024];
__device__ int g_esrc[RR * EE];                     // src per edge, bucketed by (r,dst)

// ---------------- helpers ----------------
__device__ __forceinline__ float tf32_rn(float x) {
    uint32_t u;
    asm("cvt.rna.tf32.f32 %0, %1;" : "=r"(u) : "f"(x));
    return __uint_as_float(u);
}
__device__ __forceinline__ void mma_tf32(float* d, const uint32_t* a, const uint32_t* b) {
    asm volatile(
        "mma.sync.aligned.m16n8k8.row.col.f32.tf32.tf32.f32 "
        "{%0,%1,%2,%3}, {%4,%5,%6,%7}, {%8,%9}, {%0,%1,%2,%3};"
        : "+f"(d[0]), "+f"(d[1]), "+f"(d[2]), "+f"(d[3])
        : "r"(a[0]), "r"(a[1]), "r"(a[2]), "r"(a[3]), "r"(b[0]), "r"(b[1]));
}

// ================= CSR build =================
__global__ void zero_cnt() {
    int i = blockIdx.x * blockDim.x + threadIdx.x;
    if (i < NBUK) g_cnt[i] = 0;
}
__global__ void hist_dst(const int* __restrict__ dst) {
    int i = blockIdx.x * blockDim.x + threadIdx.x;
    if (i >= RR * EE) return;
    int r = i / EE;
    atomicAdd(&g_cnt[r * NN + dst[i]], 1);
}
__global__ __launch_bounds__(1024) void scan_blk() {
    __shared__ int s[1024];
    int t = threadIdx.x;
    int i = blockIdx.x * 1024 + t;
    int v = (i < NBUK) ? g_cnt[i] : 0;
    s[t] = v;
    __syncthreads();
#pragma unroll
    for (int off = 1; off < 1024; off <<= 1) {
        int u = (t >= off) ? s[t - off] : 0;
        __syncthreads();
        s[t] += u;
        __syncthreads();
    }
    if (i < NBUK) g_off[i] = s[t] - v;
    if (t == 1023) g_bsum[blockIdx.x] = s[1023];
}
__global__ __launch_bounds__(1024) void scan_part(int nb) {
    __shared__ int s[1024];
    int t = threadIdx.x;
    int v = (t < nb) ? g_bsum[t] : 0;
    s[t] = v;
    __syncthreads();
#pragma unroll
    for (int off = 1; off < 1024; off <<= 1) {
        int u = (t >= off) ? s[t - off] : 0;
        __syncthreads();
        s[t] += u;
        __syncthreads();
    }
    g_bsum[t] = s[t] - v;
}
__global__ void scan_fix() {
    int i = blockIdx.x * blockDim.x + threadIdx.x;
    if (i >= NBUK) return;
    int o = g_off[i] + g_bsum[i >> 10];
    g_off[i] = o;
    g_cur[i] = o;
    if (i == 0) g_off[NBUK] = RR * EE;
}
__global__ void scatter_src(const int* __restrict__ src, const int* __restrict__ dst) {
    int i = blockIdx.x * blockDim.x + threadIdx.x;
    if (i >= RR * EE) return;
    int r = i / EE;
    int pos = atomicAdd(&g_cur[r * NN + dst[i]], 1);
    g_esrc[pos] = src[i];
}

// ---------------- pack weights transposed: g_Bt[c][k], tf32-rounded ----------------
__global__ void pack_Bt(const float* __restrict__ W, const float* __restrict__ loop_w) {
    int idx = blockIdx.x * blockDim.x + threadIdx.x;
    if (idx >= COLS * DIN) return;
    int c = idx >> 7, k = idx & 127;
    float v;
    if (c < RR * 128) {
        int r = c >> 7, j = c & 127;
        v = W[((size_t)r << 14) + (size_t)k * 128 + j];
    } else {
        v = loop_w[(size_t)k * 128 + (c - RR * 128)];
    }
    g_Bt[idx] = tf32_rn(v);
}

// ---------------- tf32 mma GEMM with fused el/er + self-loop epilogue ----------------
// grid (5, ceil(M/128)). bn<4: relation bn -> g_Wh(fp16) + el/er. bn==4: self+bias -> out.
#define LDS_PITCH 132
#define GEMM_SMEM (2 * 128 * LDS_PITCH * 4)
template <int H, bool RELU_A>
__global__ __launch_bounds__(256, 1) void gemm_fused(const float* __restrict__ Ain, int M,
                                                     const float* __restrict__ al,
                                                     const float* __restrict__ ar,
                                                     const float* __restrict__ bias,
                                                     float* __restrict__ outp) {
    const float* A = Ain ? Ain : g_h1;
    float* out = outp ? outp : g_h1;
    extern __shared__ float sm[];
    float (*As)[LDS_PITCH] = (float(*)[LDS_PITCH])sm;
    float (*Bs)[LDS_PITCH] = (float(*)[LDS_PITCH])(sm + 128 * LDS_PITCH);
    float (*Cs)[LDS_PITCH] = As;  // reused after MMAs

    int tid = threadIdx.x;
    int wid = tid >> 5, lane = tid & 31;
    int group = lane >> 2, tid4 = lane & 3;
    int warp_m = wid >> 1, warp_n = wid & 1;
    int bn = blockIdx.x, by = blockIdx.y;

    // ---- stage A (tf32-rounded, optional relu) ----
    {
        int row = tid >> 1;
        int colb = (tid & 1) * 64;
        int grow = by * 128 + row;
        const float4* ap = (grow < M) ? (const float4*)(A + (size_t)grow * DIN + colb) : nullptr;
#pragma unroll
        for (int j = 0; j < 16; j++) {
            float4 v = ap ? __ldg(ap + j) : make_float4(0.f, 0.f, 0.f, 0.f);
            if (RELU_A) {
                v.x = fmaxf(v.x, 0.f); v.y = fmaxf(v.y, 0.f);
                v.z = fmaxf(v.z, 0.f); v.w = fmaxf(v.w, 0.f);
            }
            *(float4*)(&As[row][colb + j * 4]) =
                make_float4(tf32_rn(v.x), tf32_rn(v.y), tf32_rn(v.z), tf32_rn(v.w));
        }
    }
    // ---- stage B ----
    {
        int row = tid >> 1;
        int colb = (tid & 1) * 64;
        const float4* bp = (const float4*)(g_Bt + (size_t)(bn * 128 + row) * DIN + colb);
#pragma unroll
        for (int j = 0; j < 16; j++)
            *(float4*)(&Bs[row][colb + j * 4]) = __ldg(bp + j);
    }
    __syncthreads();

    float acc[2][8][4] = {};
    int m0 = warp_m * 32;
    int n0 = warp_n * 64;

#pragma unroll
    for (int ks = 0; ks < 16; ks++) {
        int k0 = ks * 8;
        uint32_t afr[2][4];
#pragma unroll
        for (int mt = 0; mt < 2; mt++) {
            int mr = m0 + mt * 16;
            afr[mt][0] = __float_as_uint(As[mr + group][k0 + tid4]);
            afr[mt][1] = __float_as_uint(As[mr + group + 8][k0 + tid4]);
            afr[mt][2] = __float_as_uint(As[mr + group][k0 + tid4 + 4]);
            afr[mt][3] = __float_as_uint(As[mr + group + 8][k0 + tid4 + 4]);
        }
#pragma unroll
        for (int nt = 0; nt < 8; nt++) {
            int nc = n0 + nt * 8;
            uint32_t bfr[2];
            bfr[0] = __float_as_uint(Bs[nc + group][k0 + tid4]);
            bfr[1] = __float_as_uint(Bs[nc + group][k0 + tid4 + 4]);
            mma_tf32(acc[0][nt], afr[0], bfr);
            mma_tf32(acc[1][nt], afr[1], bfr);
        }
    }

    if (bn < RR) {
        // ---- store Wh tile in fp16 (relation-major) ----
#pragma unroll
        for (int mt = 0; mt < 2; mt++) {
            int row = by * 128 + m0 + mt * 16 + group;
#pragma unroll
            for (int nt = 0; nt < 8; nt++) {
                int col = n0 + nt * 8 + tid4 * 2;
                if (row < M)
                    *(__half2*)(g_Wh + ((size_t)bn * NN + row) * DIN + col) =
                        __floats2half2_rn(acc[mt][nt][0], acc[mt][nt][1]);
                if (row + 8 < M)
                    *(__half2*)(g_Wh + ((size_t)bn * NN + row + 8) * DIN + col) =
                        __floats2half2_rn(acc[mt][nt][2], acc[mt][nt][3]);
            }
        }
        // ---- stage C into smem for el/er ----
        __syncthreads();
#pragma unroll
        for (int mt = 0; mt < 2; mt++) {
            int rl = m0 + mt * 16 + group;
#pragma unroll
            for (int nt = 0; nt < 8; nt++) {
                int cl = n0 + nt * 8 + tid4 * 2;
                *(float2*)(&Cs[rl][cl]) = make_float2(acc[mt][nt][0], acc[mt][nt][1]);
                *(float2*)(&Cs[rl + 8][cl]) = make_float2(acc[mt][nt][2], acc[mt][nt][3]);
            }
        }
        __syncthreads();
        // ---- el/er: 8 warps x 16 rows ----
        float4 a4 = __ldg((const float4*)(al + bn * 128 + lane * 4));
        float4 b4 = __ldg((const float4*)(ar + bn * 128 + lane * 4));
#pragma unroll 4
        for (int rr = 0; rr < 16; rr++) {
            int row = wid * 16 + rr;
            int grow = by * 128 + row;
            float4 v = *(const float4*)(&Cs[row][lane * 4]);
            float pl = v.x * a4.x + v.y * a4.y + v.z * a4.z + v.w * a4.w;
            float pr = v.x * b4.x + v.y * b4.y + v.z * b4.z + v.w * b4.w;
            if (H == 8) {
                pl += __shfl_xor_sync(~0u, pl, 1);
                pr += __shfl_xor_sync(~0u, pr, 1);
                pl += __shfl_xor_sync(~0u, pl, 2);
                pr += __shfl_xor_sync(~0u, pr, 2);
                if ((lane & 3) == 0 && grow < M) {
                    size_t o = ((size_t)bn * NN + grow) * 8 + (lane >> 2);
                    g_el[o] = pl;
                    g_er[o] = pr;
                }
            } else {
#pragma unroll
                for (int o = 16; o > 0; o >>= 1) {
                    pl += __shfl_xor_sync(~0u, pl, o);
                    pr += __shfl_xor_sync(~0u, pr, o);
                }
                if (lane == 0 && grow < M) {
                    g_el[(size_t)bn * NN + grow] = pl;
                    g_er[(size_t)bn * NN + grow] = pr;
                }
            }
        }
    } else {
        // ---- self-loop + bias -> out (fp32) ----
#pragma unroll
        for (int mt = 0; mt < 2; mt++) {
            int row = by * 128 + m0 + mt * 16 + group;
#pragma unroll
            for (int nt = 0; nt < 8; nt++) {
                int col = n0 + nt * 8 + tid4 * 2;
                float b0 = __ldg(bias + col), b1 = __ldg(bias + col + 1);
                if (row < M)
                    *(float2*)(out + (size_t)row * DIN + col) =
                        make_float2(acc[mt][nt][0] + b0, acc[mt][nt][1] + b1);
                if (row + 8 < M)
                    *(float2*)(out + (size_t)(row + 8) * DIN + col) =
                        make_float2(acc[mt][nt][2] + b0, acc[mt][nt][3] + b1);
            }
        }
    }
}

// ---------------- fused per-node kernel: all relations, register accumulation ----
// Starts from the GEMM-written (self-loop + bias) value in out[d]; overwrites it.
template <int H>
__global__ __launch_bounds__(256) void node_fused(float* __restrict__ outp, int do_relu) {
    float* out = outp ? outp : g_h1;
    int d = (blockIdx.x * blockDim.x + threadIdx.x) >> 5;
    int lane = threadIdx.x & 31;
    if (d >= NN) return;

    float4 acc = *(const float4*)(out + (size_t)d * DIN + lane * 4);

#pragma unroll
    for (int r = 0; r < RR; r++) {
        int base = r * NN + d;
        int start = g_off[base];
        int end = g_off[base + 1];
        if (start >= end) continue;
        const uint2* whr = (const uint2*)(g_Wh + (size_t)r * NN * DIN);  // 32 uint2/row
        const float* elr = g_el + (size_t)r * NN * H;

        if (H == 8) {
            int hl = lane & 7;
            float er_l = g_er[(size_t)base * 8 + hl];
            float den = 0.f;
            for (int c = start + (lane >> 3); c < end; c += 4) {
                int s = __ldg(&g_esrc[c]);
                float e = __ldg(&elr[(size_t)s * 8 + hl]) + er_l;
                e = e > 0.f ? e : 0.2f * e;
                den += expf(e);
            }
            den += __shfl_xor_sync(~0u, den, 8);
            den += __shfl_xor_sync(~0u, den, 16);
            float rden = 1.0f / den;
            int hh = lane >> 2;
            float rden_h = __shfl_sync(~0u, rden, hh);
            float er_h = __shfl_sync(~0u, er_l, hh);
            for (int c = start; c < end; c++) {
                int s = __ldg(&g_esrc[c]);
                float e = __ldg(&elr[(size_t)s * 8 + hh]) + er_h;
                e = e > 0.f ? e : 0.2f * e;
                float alpha = expf(e) * rden_h;
                uint2 u = __ldg(whr + (size_t)s * 32 + lane);
                float2 f0 = __half22float2(*(__half2*)&u.x);
                float2 f1 = __half22float2(*(__half2*)&u.y);
                acc.x += alpha * f0.x;
                acc.y += alpha * f0.y;
                acc.z += alpha * f1.x;
                acc.w += alpha * f1.y;
            }
        } else {
            float er_l = g_er[base];
            float den = 0.f;
            for (int c = start + lane; c < end; c += 32) {
                int s = __ldg(&g_esrc[c]);
                float e = __ldg(&elr[s]) + er_l;
                e = e > 0.f ? e : 0.2f * e;
                den += expf(e);
            }
#pragma unroll
            for (int o = 16; o > 0; o >>= 1) den += __shfl_xor_sync(~0u, den, o);
            float rden = 1.0f / den;
            for (int c = start; c < end; c++) {
                int s = __ldg(&g_esrc[c]);
                float e = __ldg(&elr[s]) + er_l;
                e = e > 0.f ? e : 0.2f * e;
                float alpha = expf(e) * rden;
                uint2 u = __ldg(whr + (size_t)s * 32 + lane);
                float2 f0 = __half22float2(*(__half2*)&u.x);
                float2 f1 = __half22float2(*(__half2*)&u.y);
                acc.x += alpha * f0.x;
                acc.y += alpha * f0.y;
                acc.z += alpha * f1.x;
                acc.w += alpha * f1.y;
            }
        }
    }

    if (do_relu) {
        acc.x = fmaxf(acc.x, 0.f);
        acc.y = fmaxf(acc.y, 0.f);
        acc.z = fmaxf(acc.z, 0.f);
        acc.w = fmaxf(acc.w, 0.f);
    }
    *(float4*)(out + (size_t)d * DIN + lane * 4) = acc;
}

extern "C" void kernel_launch(void* const* d_in, const int* in_sizes, int n_in,
                              void* d_out, int out_size) {
    const float* h   = (const float*)d_in[0];
    const int*   src = (const int*)d_in[1];
    const int*   dst = (const int*)d_in[2];
    const float* W1  = (const float*)d_in[3];
    const float* al1 = (const float*)d_in[4];
    const float* ar1 = (const float*)d_in[5];
    const float* lp1 = (const float*)d_in[6];
    const float* b1  = (const float*)d_in[7];
    const float* W2  = (const float*)d_in[8];
    const float* al2 = (const float*)d_in[9];
    const float* ar2 = (const float*)d_in[10];
    const float* lp2 = (const float*)d_in[11];
    const float* b2  = (const float*)d_in[12];
    float* out = (float*)d_out;

    static bool attr_set = false;
    if (!attr_set) {
        cudaFuncSetAttribute(gemm_fused<8, false>,
                             cudaFuncAttributeMaxDynamicSharedMemorySize, GEMM_SMEM);
        cudaFuncSetAttribute(gemm_fused<1, true>,
                             cudaFuncAttributeMaxDynamicSharedMemorySize, GEMM_SMEM);
        attr_set = true;
    }

    const int nb1 = (NBUK + 1023) / 1024;
    const dim3 ggrid(RR + 1, (NN + 127) / 128);
    const int nblk = (NN * 32 + 255) / 256;

    // ---- CSR build (graph shared by both layers) ----
    zero_cnt<<<(NBUK + 255) / 256, 256>>>();
    hist_dst<<<(RR * EE + 255) / 256, 256>>>(dst);
    scan_blk<<<nb1, 1024>>>();
    scan_part<<<1, 1024>>>(nb1);
    scan_fix<<<(NBUK + 255) / 256, 256>>>();
    scatter_src<<<(RR * EE + 255) / 256, 256>>>(src, dst);

    // ---- Layer 1 (H=8): gemm -> Wh/el/er + (self+bias)->g_h1; fused node pass ----
    pack_Bt<<<(COLS * DIN + 255) / 256, 256>>>(W1, lp1);
    gemm_fused<8, false><<<ggrid, 256, GEMM_SMEM>>>(h, NN, al1, ar1, b1, nullptr);
    node_fused<8><<<nblk, 256>>>(nullptr, 1);

    // ---- Layer 2 (H=1): relu folded into A-load; result -> d_out ----
    pack_Bt<<<(COLS * DIN + 255) / 256, 256>>>(W2, lp2);
    gemm_fused<1, true><<<ggrid, 256, GEMM_SMEM>>>(nullptr, NN, al2, ar2, b2, out);
    node_fused<1><<<nblk, 256>>>(out, 0);

    (void)in_sizes; (void)n_in; (void)out_size;
}